// round 3
// baseline (speedup 1.0000x reference)
#include <cuda_runtime.h>
#include <cuda_bf16.h>

// Problem constants (fixed by the reference setup)
#define B_    64
#define NA_   2048
#define NTOT_ (B_ * NA_)        // 131072 atoms
#define EG_   40960             // directed edges per graph
#define E_    (B_ * EG_)        // 2,621,440 input edges
#define E2_   (2 * E_)          // 5,242,880 symmetrized edges

// Output layout: tuple members flattened row-major and concatenated, cast to f32
// (ei_sym[2,E2], off_sym[E2,3], dist[E2], vec[E2,3], nn_sym[B], id_swap[E2])
#define BASE_EI   0
#define BASE_OFF  (2 * E2_)                 // 10,485,760
#define BASE_DIST (BASE_OFF + 3 * E2_)      // 26,214,400
#define BASE_VEC  (BASE_DIST + E2_)         // 31,457,280
#define BASE_NN   (BASE_VEC + 3 * E2_)      // 47,185,920
#define BASE_SWAP (BASE_NN + B_)            // 47,185,984
// total = BASE_SWAP + E2_ = 52,428,864 f32 elements

// Runtime dtype flag: 1 if edge_index / num_neighbors are int64, 0 if int32.
__device__ int g_is64;

__global__ void detect_kernel(const unsigned long long* __restrict__ ei) {
    if (threadIdx.x == 0) {
        int is64 = 1;
        // True int64 atom indices are < 2^31. int32 data read as u64 packs two
        // indices per word; within 64 words at least one high half is nonzero.
        #pragma unroll
        for (int k = 0; k < 64; ++k)
            if (ei[k] >= (1ULL << 31)) { is64 = 0; break; }
        g_is64 = is64;
    }
}

__global__ __launch_bounds__(256)
void graph_edges_kernel(const float* __restrict__ pos,
                        const float* __restrict__ cell,
                        const void*  __restrict__ ei_raw,
                        const int*   __restrict__ off,
                        float*       __restrict__ out)
{
    const int e = blockIdx.x * 256 + threadIdx.x;
    if (e >= E_) return;

    const int b = e / EG_;                 // graph id (block never straddles: 40960 % 256 == 0)
    const int is64 = g_is64;

    int iv, jv;
    if (is64) {
        const long long* ei = (const long long*)ei_raw;
        iv = (int)__ldg(&ei[e]);
        jv = (int)__ldg(&ei[E_ + e]);
    } else {
        const int* ei = (const int*)ei_raw;
        iv = __ldg(&ei[e]);
        jv = __ldg(&ei[E_ + e]);
    }

    const int o0 = __ldg(&off[3 * e + 0]);
    const int o1 = __ldg(&off[3 * e + 1]);
    const int o2 = __ldg(&off[3 * e + 2]);

    // offsets = cell_offset[e] @ cell[b]   (einsum 'ec,ecd->ed')
    const float* cb = cell + 9 * b;        // broadcast load, L1-resident
    const float f0 = (float)o0, f1 = (float)o1, f2 = (float)o2;
    const float ox = f0 * cb[0] + f1 * cb[3] + f2 * cb[6];
    const float oy = f0 * cb[1] + f1 * cb[4] + f2 * cb[7];
    const float oz = f0 * cb[2] + f1 * cb[5] + f2 * cb[8];

    // distance_vec = pos[i] - pos[j] + offsets
    const float dx = __ldg(&pos[3 * iv + 0]) - __ldg(&pos[3 * jv + 0]) + ox;
    const float dy = __ldg(&pos[3 * iv + 1]) - __ldg(&pos[3 * jv + 1]) + oy;
    const float dz = __ldg(&pos[3 * iv + 2]) - __ldg(&pos[3 * jv + 2]) + oz;

    const float dist = sqrtf(dx * dx + dy * dy + dz * dz);
    const float inv  = 1.0f / dist;
    const float vx = -dx * inv, vy = -dy * inv, vz = -dz * inv;

    // symmetrized slots: fwd f = e + b*EG, bwd w = f + EG
    const int f = e + b * EG_;
    const int w = f + EG_;

    // ei_sym [2, E2]
    out[BASE_EI + f]       = (float)iv;
    out[BASE_EI + E2_ + f] = (float)jv;
    out[BASE_EI + w]       = (float)jv;
    out[BASE_EI + E2_ + w] = (float)iv;

    // off_sym [E2, 3]
    float* po = out + BASE_OFF;
    po[3 * f + 0] = f0;  po[3 * f + 1] = f1;  po[3 * f + 2] = f2;
    po[3 * w + 0] = -f0; po[3 * w + 1] = -f1; po[3 * w + 2] = -f2;

    // dist_sym [E2]
    out[BASE_DIST + f] = dist;
    out[BASE_DIST + w] = dist;

    // vec_sym [E2, 3]
    float* pv = out + BASE_VEC;
    pv[3 * f + 0] = vx;  pv[3 * f + 1] = vy;  pv[3 * f + 2] = vz;
    pv[3 * w + 0] = -vx; pv[3 * w + 1] = -vy; pv[3 * w + 2] = -vz;

    // id_swap_edge_index [E2]: analytically the fwd/bwd twin permutation.
    out[BASE_SWAP + f] = (float)w;
    out[BASE_SWAP + w] = (float)f;
}

__global__ void nn_kernel(const void* __restrict__ nn_raw, float* __restrict__ out) {
    const int t = threadIdx.x;
    if (t < B_) {
        long long v;
        if (g_is64) v = ((const long long*)nn_raw)[t];
        else        v = ((const int*)nn_raw)[t];
        out[BASE_NN + t] = (float)(2 * v);
    }
}

extern "C" void kernel_launch(void* const* d_in, const int* in_sizes, int n_in,
                              void* d_out, int out_size) {
    const float* pos  = (const float*)d_in[0];   // [N,3] f32
    const float* cell = (const float*)d_in[1];   // [B,3,3] f32
    const void*  ei   = d_in[2];                 // [2,E] int64 or int32
    const int*   off  = (const int*)d_in[3];     // [E,3] int32
    const void*  nn   = d_in[4];                 // [B] int64 or int32
    float* out = (float*)d_out;

    detect_kernel<<<1, 32>>>((const unsigned long long*)ei);
    graph_edges_kernel<<<E_ / 256, 256>>>(pos, cell, ei, off, out);
    nn_kernel<<<1, 64>>>(nn, out);
}

// round 4
// speedup vs baseline: 1.0904x; 1.0904x over previous
#include <cuda_runtime.h>
#include <cuda_bf16.h>

// Problem constants (fixed by the reference setup)
#define B_    64
#define NA_   2048
#define NTOT_ (B_ * NA_)        // 131072 atoms
#define EG_   40960             // directed edges per graph
#define E_    (B_ * EG_)        // 2,621,440 input edges
#define E2_   (2 * E_)          // 5,242,880 symmetrized edges

// Output layout: tuple members flattened row-major and concatenated, cast to f32
#define BASE_EI   0
#define BASE_OFF  (2 * E2_)                 // 10,485,760
#define BASE_DIST (BASE_OFF + 3 * E2_)      // 26,214,400
#define BASE_VEC  (BASE_DIST + E2_)         // 31,457,280
#define BASE_NN   (BASE_VEC + 3 * E2_)      // 47,185,920
#define BASE_SWAP (BASE_NN + B_)            // 47,185,984

// Scratch: float4-padded positions for single-LDG.128 gathers (2 MB, static).
__device__ float4 d_posh[NTOT_];
// Runtime dtype flag: 1 if edge_index / num_neighbors are int64, 0 if int32.
__device__ int g_is64;

// Prep: pad pos -> float4 scratch; block 0 additionally detects the index
// dtype and emits the num_neighbors_sym output (folds 2 tiny kernels into 1).
__global__ __launch_bounds__(256)
void prep_kernel(const float* __restrict__ pos,
                 const unsigned long long* __restrict__ ei_u64,
                 const void* __restrict__ nn_raw,
                 float* __restrict__ out)
{
    const int t = blockIdx.x * 256 + threadIdx.x;
    if (t < NTOT_) {
        float4 p;
        p.x = pos[3 * t + 0];
        p.y = pos[3 * t + 1];
        p.z = pos[3 * t + 2];
        p.w = 0.0f;
        d_posh[t] = p;
    }
    if (blockIdx.x == 0) {
        __shared__ int s64;
        if (threadIdx.x == 0) {
            int is64 = 1;
            // True int64 atom indices are < 2^31. int32 data reinterpreted as
            // u64 packs two indices per word; among 8 words the high half
            // (a source index) is nonzero w.o.p. for this dataset.
            #pragma unroll
            for (int k = 0; k < 8; ++k)
                if (ei_u64[k] >= (1ULL << 31)) { is64 = 0; break; }
            g_is64 = is64;
            s64 = is64;
        }
        __syncthreads();
        if (threadIdx.x < B_) {
            long long v;
            if (s64) v = ((const long long*)nn_raw)[threadIdx.x];
            else     v = (long long)((const int*)nn_raw)[threadIdx.x];
            out[BASE_NN + threadIdx.x] = (float)(2 * v);
        }
    }
}

__global__ __launch_bounds__(256)
void graph_edges_kernel(const float* __restrict__ cell,
                        const void*  __restrict__ ei_raw,
                        const int*   __restrict__ off,
                        float*       __restrict__ out)
{
    const int e = blockIdx.x * 256 + threadIdx.x;   // grid exactly covers E_
    const int b = e / EG_;          // graph id (block never straddles: 40960 % 256 == 0)

    int iv, jv;
    if (g_is64) {
        const long long* ei = (const long long*)ei_raw;
        iv = (int)__ldg(&ei[e]);
        jv = (int)__ldg(&ei[E_ + e]);
    } else {
        const int* ei = (const int*)ei_raw;
        iv = __ldg(&ei[e]);
        jv = __ldg(&ei[E_ + e]);
    }

    const int o0 = __ldg(&off[3 * e + 0]);
    const int o1 = __ldg(&off[3 * e + 1]);
    const int o2 = __ldg(&off[3 * e + 2]);

    // offsets = cell_offset[e] @ cell[b]   (einsum 'ec,ecd->ed'); cell broadcast, L1-hit
    const float* cb = cell + 9 * b;
    const float f0 = (float)o0, f1 = (float)o1, f2 = (float)o2;
    const float ox = f0 * cb[0] + f1 * cb[3] + f2 * cb[6];
    const float oy = f0 * cb[1] + f1 * cb[4] + f2 * cb[7];
    const float oz = f0 * cb[2] + f1 * cb[5] + f2 * cb[8];

    // Single 128-bit gather per endpoint (padded pos)
    const float4 pi = d_posh[iv];
    const float4 pj = d_posh[jv];

    const float dx = pi.x - pj.x + ox;
    const float dy = pi.y - pj.y + oy;
    const float dz = pi.z - pj.z + oz;

    const float dist = sqrtf(dx * dx + dy * dy + dz * dz);
    const float inv  = 1.0f / dist;
    const float vx = -dx * inv, vy = -dy * inv, vz = -dz * inv;

    // symmetrized slots: fwd f = e + b*EG, bwd w = f + EG
    const int f = e + b * EG_;
    const int w = f + EG_;

    // ei_sym [2, E2]
    __stcs(&out[BASE_EI + f],        (float)iv);
    __stcs(&out[BASE_EI + E2_ + f],  (float)jv);
    __stcs(&out[BASE_EI + w],        (float)jv);
    __stcs(&out[BASE_EI + E2_ + w],  (float)iv);

    // off_sym [E2, 3]
    float* po = out + BASE_OFF;
    __stcs(&po[3 * f + 0], f0);  __stcs(&po[3 * f + 1], f1);  __stcs(&po[3 * f + 2], f2);
    __stcs(&po[3 * w + 0], -f0); __stcs(&po[3 * w + 1], -f1); __stcs(&po[3 * w + 2], -f2);

    // dist_sym [E2]
    __stcs(&out[BASE_DIST + f], dist);
    __stcs(&out[BASE_DIST + w], dist);

    // vec_sym [E2, 3]
    float* pv = out + BASE_VEC;
    __stcs(&pv[3 * f + 0], vx);  __stcs(&pv[3 * f + 1], vy);  __stcs(&pv[3 * f + 2], vz);
    __stcs(&pv[3 * w + 0], -vx); __stcs(&pv[3 * w + 1], -vy); __stcs(&pv[3 * w + 2], -vz);

    // id_swap_edge_index [E2]: analytically the fwd/bwd twin permutation.
    __stcs(&out[BASE_SWAP + f], (float)w);
    __stcs(&out[BASE_SWAP + w], (float)f);
}

extern "C" void kernel_launch(void* const* d_in, const int* in_sizes, int n_in,
                              void* d_out, int out_size) {
    const float* pos  = (const float*)d_in[0];   // [N,3] f32
    const float* cell = (const float*)d_in[1];   // [B,3,3] f32
    const void*  ei   = d_in[2];                 // [2,E] int64 or int32
    const int*   off  = (const int*)d_in[3];     // [E,3] int32
    const void*  nn   = d_in[4];                 // [B] int64 or int32
    float* out = (float*)d_out;

    prep_kernel<<<(NTOT_ + 255) / 256, 256>>>(pos, (const unsigned long long*)ei, nn, out);
    graph_edges_kernel<<<E_ / 256, 256>>>(cell, ei, off, out);
}

// round 6
// speedup vs baseline: 1.2025x; 1.1028x over previous
#include <cuda_runtime.h>
#include <cuda_bf16.h>

// Problem constants (fixed by the reference setup)
#define B_    64
#define NA_   2048
#define NTOT_ (B_ * NA_)        // 131072 atoms
#define EG_   40960             // directed edges per graph
#define E_    (B_ * EG_)        // 2,621,440 input edges
#define E2_   (2 * E_)          // 5,242,880 symmetrized edges

#define EPB_      4096          // edges per block (EG_ % EPB_ == 0 -> 10 blocks/graph)
#define THREADS_  512
#define ITERS_    (EPB_ / THREADS_)   // 8
#define GRID_     (E_ / EPB_)         // 640

// Output layout: tuple members flattened row-major and concatenated, cast to f32
#define BASE_EI   0
#define BASE_OFF  (2 * E2_)                 // 10,485,760
#define BASE_DIST (BASE_OFF + 3 * E2_)      // 26,214,400
#define BASE_VEC  (BASE_DIST + E2_)         // 31,457,280
#define BASE_NN   (BASE_VEC + 3 * E2_)      // 47,185,920
#define BASE_SWAP (BASE_NN + B_)            // 47,185,984

__global__ __launch_bounds__(THREADS_)
void graph_edges_kernel(const float* __restrict__ pos,
                        const float* __restrict__ cell,
                        const void*  __restrict__ ei_raw,
                        const int*   __restrict__ off,
                        const void*  __restrict__ nn_raw,
                        float*       __restrict__ out)
{
    __shared__ float4 s_pos[NA_];          // 32 KB: this graph's padded positions
    __shared__ int    s_is64;

    const int tid = threadIdx.x;
    const int blk = blockIdx.x;
    const int b     = blk / (EG_ / EPB_);  // graph id
    const int chunk = blk % (EG_ / EPB_);
    const int e0    = b * EG_ + chunk * EPB_;

    // Per-block dtype detection: true int64 atom indices are < 2^31; int32
    // data reinterpreted as u64 packs a (nonzero w.o.p.) src index in the
    // high half within the first 8 words.
    if (tid == 0) {
        const unsigned long long* eu = (const unsigned long long*)ei_raw;
        int is64 = 1;
        #pragma unroll
        for (int k = 0; k < 8; ++k)
            if (eu[k] >= (1ULL << 31)) { is64 = 0; break; }
        s_is64 = is64;
    }

    // Cooperative coalesced load of this graph's positions, padded to float4.
    {
        const float* pb = pos + (size_t)b * NA_ * 3;
        float* sp = (float*)s_pos;
        #pragma unroll
        for (int i = tid; i < NA_ * 3; i += THREADS_) {
            const int atom = i / 3;
            const int comp = i - atom * 3;
            sp[atom * 4 + comp] = pb[i];
        }
    }
    __syncthreads();
    const int is64 = s_is64;

    // cell[b] broadcast (L1-resident)
    const float* cb = cell + 9 * b;
    const float c00 = cb[0], c01 = cb[1], c02 = cb[2];
    const float c10 = cb[3], c11 = cb[4], c12 = cb[5];
    const float c20 = cb[6], c21 = cb[7], c22 = cb[8];

    const int abase = b * NA_;

    #pragma unroll
    for (int k = 0; k < ITERS_; ++k) {
        const int e = e0 + k * THREADS_ + tid;

        int iv, jv;
        if (is64) {
            const long long* ei = (const long long*)ei_raw;
            iv = (int)__ldg(&ei[e]);
            jv = (int)__ldg(&ei[E_ + e]);
        } else {
            const int* ei = (const int*)ei_raw;
            iv = __ldg(&ei[e]);
            jv = __ldg(&ei[E_ + e]);
        }

        const float f0 = (float)__ldg(&off[3 * e + 0]);
        const float f1 = (float)__ldg(&off[3 * e + 1]);
        const float f2 = (float)__ldg(&off[3 * e + 2]);

        // offsets = cell_offset[e] @ cell[b]
        const float ox = f0 * c00 + f1 * c10 + f2 * c20;
        const float oy = f0 * c01 + f1 * c11 + f2 * c21;
        const float oz = f0 * c02 + f1 * c12 + f2 * c22;

        // smem gathers (LDS.128) — off the l1tex global path
        const float4 pi = s_pos[iv - abase];
        const float4 pj = s_pos[jv - abase];

        const float dx = pi.x - pj.x + ox;
        const float dy = pi.y - pj.y + oy;
        const float dz = pi.z - pj.z + oz;

        const float dist = sqrtf(dx * dx + dy * dy + dz * dz);
        const float inv  = 1.0f / dist;
        const float vx = -dx * inv, vy = -dy * inv, vz = -dz * inv;

        // symmetrized slots: fwd f = e + b*EG, bwd w = f + EG
        const int f = e + b * EG_;
        const int w = f + EG_;

        // ei_sym [2, E2]
        __stcs(&out[BASE_EI + f],        (float)iv);
        __stcs(&out[BASE_EI + E2_ + f],  (float)jv);
        __stcs(&out[BASE_EI + w],        (float)jv);
        __stcs(&out[BASE_EI + E2_ + w],  (float)iv);

        // off_sym [E2, 3]
        float* po = out + BASE_OFF;
        __stcs(&po[3 * f + 0], f0);  __stcs(&po[3 * f + 1], f1);  __stcs(&po[3 * f + 2], f2);
        __stcs(&po[3 * w + 0], -f0); __stcs(&po[3 * w + 1], -f1); __stcs(&po[3 * w + 2], -f2);

        // dist_sym [E2]
        __stcs(&out[BASE_DIST + f], dist);
        __stcs(&out[BASE_DIST + w], dist);

        // vec_sym [E2, 3]
        float* pv = out + BASE_VEC;
        __stcs(&pv[3 * f + 0], vx);  __stcs(&pv[3 * f + 1], vy);  __stcs(&pv[3 * f + 2], vz);
        __stcs(&pv[3 * w + 0], -vx); __stcs(&pv[3 * w + 1], -vy); __stcs(&pv[3 * w + 2], -vz);

        // id_swap_edge_index [E2]: analytically the fwd/bwd twin permutation.
        __stcs(&out[BASE_SWAP + f], (float)w);
        __stcs(&out[BASE_SWAP + w], (float)f);
    }

    // num_neighbors_sym (block 0 only)
    if (blk == 0 && tid < B_) {
        long long v;
        if (is64) v = ((const long long*)nn_raw)[tid];
        else      v = (long long)((const int*)nn_raw)[tid];
        out[BASE_NN + tid] = (float)(2 * v);
    }
}

extern "C" void kernel_launch(void* const* d_in, const int* in_sizes, int n_in,
                              void* d_out, int out_size) {
    const float* pos  = (const float*)d_in[0];   // [N,3] f32
    const float* cell = (const float*)d_in[1];   // [B,3,3] f32
    const void*  ei   = d_in[2];                 // [2,E] int64 or int32
    const int*   off  = (const int*)d_in[3];     // [E,3] int32
    const void*  nn   = d_in[4];                 // [B] int64 or int32
    float* out = (float*)d_out;

    graph_edges_kernel<<<GRID_, THREADS_>>>(pos, cell, ei, off, nn, out);
}